// round 1
// baseline (speedup 1.0000x reference)
#include <cuda_runtime.h>
#include <math.h>

#define BB    64
#define DD    256
#define HEADS 8
#define DH    32
#define NTOK  625
#define NPAD  640
#define NQT   10      // ceil(625/64)

// ---- scratch (device globals: allocation-free per harness rules) ----
__device__ float g_q[BB*HEADS*NTOK*DH];
__device__ float g_k[BB*HEADS*NTOK*DH];
__device__ float g_v[BB*HEADS*NTOK*DH];
__device__ float g_bias[HEADS*NPAD*NPAD];
__device__ float g_o[BB*NTOK*DD];

// ============================================================
// Kernel 0: bias_fill — bias[h][i][j] = table[rel[i*625+j]*8+h]
// padded j-stride 640 so attention reads are float4-aligned
// ============================================================
__global__ void bias_fill(const float* __restrict__ table,
                          const int*   __restrict__ rel) {
    int idx = blockIdx.x * blockDim.x + threadIdx.x;
    const int total = HEADS * NTOK * NTOK;
    if (idx >= total) return;
    int h = idx / (NTOK * NTOK);
    int r = idx - h * (NTOK * NTOK);
    int i = r / NTOK;
    int j = r - i * NTOK;
    g_bias[(h * NPAD + i) * NPAD + j] = table[rel[r] * HEADS + h];
}

// ============================================================
// Kernel 1: QKV GEMM.  A[p][c] = x[b][c][p] (stride-625),
// B = w_qkv (256x768).  Output scattered to q/k/v in (b,h,p,e)
// layout; q pre-scaled by dh^-0.5.
// ============================================================
__global__ void qkv_gemm(const float* __restrict__ x,
                         const float* __restrict__ w) {
    __shared__ float As[16][64];
    __shared__ float Bs[16][64];
    int b  = blockIdx.z;
    int p0 = blockIdx.x * 64;
    int n0 = blockIdx.y * 64;
    int tid = threadIdx.x;
    int tx = tid & 15, ty = tid >> 4;

    float acc[4][4] = {};
    int lp = tid & 63;   // load lane: p (A) / n (B)
    int lw = tid >> 6;   // 0..3
    int p  = p0 + lp;
    const float* xb = x + (size_t)b * DD * NTOK;

    for (int kt = 0; kt < DD; kt += 16) {
        #pragma unroll
        for (int i = 0; i < 4; i++) {
            int c = lw + i * 4;
            As[c][lp] = (p < NTOK) ? xb[(kt + c) * NTOK + p] : 0.f;
            Bs[c][lp] = w[(kt + c) * (3 * DD) + n0 + lp];
        }
        __syncthreads();
        #pragma unroll
        for (int k = 0; k < 16; k++) {
            float4 a4 = *(const float4*)&As[k][ty * 4];
            float4 b4 = *(const float4*)&Bs[k][tx * 4];
            float am[4] = {a4.x, a4.y, a4.z, a4.w};
            float bn[4] = {b4.x, b4.y, b4.z, b4.w};
            #pragma unroll
            for (int i = 0; i < 4; i++)
                #pragma unroll
                for (int j = 0; j < 4; j++)
                    acc[i][j] = fmaf(am[i], bn[j], acc[i][j]);
        }
        __syncthreads();
    }

    int ng    = n0 + tx * 4;
    int which = ng >> 8;             // 0=q 1=k 2=v (64-tile never crosses)
    int hh    = (ng >> 5) & 7;
    int e0    = ng & 31;
    float* dst = (which == 0) ? g_q : (which == 1) ? g_k : g_v;
    float s = (which == 0) ? 0.17677669529663687f : 1.f;   // 32^-0.5
    int bh = b * HEADS + hh;
    #pragma unroll
    for (int mm = 0; mm < 4; mm++) {
        int pp = p0 + ty * 4 + mm;
        if (pp < NTOK) {
            float4 v = make_float4(acc[mm][0]*s, acc[mm][1]*s,
                                   acc[mm][2]*s, acc[mm][3]*s);
            *(float4*)&dst[((size_t)(bh * NTOK + pp)) * DH + e0] = v;
        }
    }
}

// ============================================================
// Kernel 2: flash attention.  Block = (q-tile of 64, b*h).
// K/V tiles in smem; online softmax; P·V via smem round-trip.
// ============================================================
__global__ void attn_kernel() {
    __shared__ float Qs[64][33];   // pad 33: K/Q reads 2-way worst
    __shared__ float Ks[64][33];
    __shared__ float Vs[64][34];   // pad 34: aligned float2, even banks
    __shared__ float Ss[64][68];   // pad 68: aligned float4 writes

    int q0 = blockIdx.x * 64;
    int bh = blockIdx.y;
    int h  = bh & 7;
    int b  = bh >> 3;
    int tid = threadIdx.x;
    int tx = tid & 15, ty = tid >> 4;

    const float* qb = g_q + (size_t)bh * NTOK * DH;
    const float* kb = g_k + (size_t)bh * NTOK * DH;
    const float* vb = g_v + (size_t)bh * NTOK * DH;

    // load Q tile (rows >= 625 -> 0)
    {
        int row = tid >> 2;
        int e0  = (tid & 3) * 8;
        int p   = q0 + row;
        float4 v0, v1;
        if (p < NTOK) {
            v0 = *(const float4*)&qb[(size_t)p * DH + e0];
            v1 = *(const float4*)&qb[(size_t)p * DH + e0 + 4];
        } else { v0 = make_float4(0,0,0,0); v1 = v0; }
        Qs[row][e0+0]=v0.x; Qs[row][e0+1]=v0.y; Qs[row][e0+2]=v0.z; Qs[row][e0+3]=v0.w;
        Qs[row][e0+4]=v1.x; Qs[row][e0+5]=v1.y; Qs[row][e0+6]=v1.z; Qs[row][e0+7]=v1.w;
    }

    float oa[4][2] = {};
    float mr[4], lr[4];
    #pragma unroll
    for (int i = 0; i < 4; i++) { mr[i] = -INFINITY; lr[i] = 0.f; }

    for (int t = 0; t < NQT; t++) {
        int j0 = t * 64;
        // load K, V tile
        {
            int row = tid >> 2;
            int e0  = (tid & 3) * 8;
            int jp  = j0 + row;
            float4 k0, k1, w0, w1;
            if (jp < NTOK) {
                k0 = *(const float4*)&kb[(size_t)jp * DH + e0];
                k1 = *(const float4*)&kb[(size_t)jp * DH + e0 + 4];
                w0 = *(const float4*)&vb[(size_t)jp * DH + e0];
                w1 = *(const float4*)&vb[(size_t)jp * DH + e0 + 4];
            } else {
                k0 = make_float4(0,0,0,0); k1 = k0; w0 = k0; w1 = k0;
            }
            Ks[row][e0+0]=k0.x; Ks[row][e0+1]=k0.y; Ks[row][e0+2]=k0.z; Ks[row][e0+3]=k0.w;
            Ks[row][e0+4]=k1.x; Ks[row][e0+5]=k1.y; Ks[row][e0+6]=k1.z; Ks[row][e0+7]=k1.w;
            Vs[row][e0+0]=w0.x; Vs[row][e0+1]=w0.y; Vs[row][e0+2]=w0.z; Vs[row][e0+3]=w0.w;
            Vs[row][e0+4]=w1.x; Vs[row][e0+5]=w1.y; Vs[row][e0+6]=w1.z; Vs[row][e0+7]=w1.w;
        }
        __syncthreads();

        // S = Q K^T  (4x4 micro-tile per thread)
        float sacc[4][4] = {};
        #pragma unroll
        for (int e = 0; e < 32; e++) {
            float qv[4], kv[4];
            #pragma unroll
            for (int i = 0; i < 4; i++) qv[i] = Qs[ty*4 + i][e];
            #pragma unroll
            for (int j = 0; j < 4; j++) kv[j] = Ks[tx*4 + j][e];
            #pragma unroll
            for (int i = 0; i < 4; i++)
                #pragma unroll
                for (int j = 0; j < 4; j++)
                    sacc[i][j] = fmaf(qv[i], kv[j], sacc[i][j]);
        }

        // + bias, mask tail
        {
            const float* brow = g_bias
                + ((size_t)(h * NPAD + q0 + ty * 4)) * NPAD + j0 + tx * 4;
            #pragma unroll
            for (int i = 0; i < 4; i++) {
                float4 bv = *(const float4*)(brow + (size_t)i * NPAD);
                sacc[i][0] += bv.x; sacc[i][1] += bv.y;
                sacc[i][2] += bv.z; sacc[i][3] += bv.w;
            }
            if (j0 + 64 > NTOK) {
                #pragma unroll
                for (int j = 0; j < 4; j++)
                    if (j0 + tx * 4 + j >= NTOK) {
                        #pragma unroll
                        for (int i = 0; i < 4; i++) sacc[i][j] = -1e30f;
                    }
            }
        }

        // online softmax per row (row = half-warp of 16 lanes)
        #pragma unroll
        for (int i = 0; i < 4; i++) {
            float rmax = fmaxf(fmaxf(sacc[i][0], sacc[i][1]),
                               fmaxf(sacc[i][2], sacc[i][3]));
            #pragma unroll
            for (int off = 8; off; off >>= 1)
                rmax = fmaxf(rmax, __shfl_xor_sync(0xffffffffu, rmax, off));
            float mnew = fmaxf(mr[i], rmax);
            float corr = __expf(mr[i] - mnew);
            float e0 = __expf(sacc[i][0] - mnew);
            float e1 = __expf(sacc[i][1] - mnew);
            float e2 = __expf(sacc[i][2] - mnew);
            float e3 = __expf(sacc[i][3] - mnew);
            float ps = (e0 + e1) + (e2 + e3);
            #pragma unroll
            for (int off = 8; off; off >>= 1)
                ps += __shfl_xor_sync(0xffffffffu, ps, off);
            lr[i] = lr[i] * corr + ps;
            mr[i] = mnew;
            oa[i][0] *= corr; oa[i][1] *= corr;
            *(float4*)&Ss[ty*4 + i][tx*4] = make_float4(e0, e1, e2, e3);
        }
        __syncthreads();

        // O += P V   (4 rows x 2 cols per thread)
        #pragma unroll 4
        for (int k = 0; k < 64; k++) {
            float2 vv = *(const float2*)&Vs[k][tx * 2];
            #pragma unroll
            for (int i = 0; i < 4; i++) {
                float pp = Ss[ty*4 + i][k];
                oa[i][0] = fmaf(pp, vv.x, oa[i][0]);
                oa[i][1] = fmaf(pp, vv.y, oa[i][1]);
            }
        }
        __syncthreads();
    }

    // write O in (b, p, h*32+e) layout for the output projection
    #pragma unroll
    for (int i = 0; i < 4; i++) {
        int p = q0 + ty * 4 + i;
        if (p < NTOK) {
            float inv = 1.f / lr[i];
            float2 o2 = make_float2(oa[i][0] * inv, oa[i][1] * inv);
            *(float2*)&g_o[((size_t)b * NTOK + p) * DD + h * DH + tx * 2] = o2;
        }
    }
}

// ============================================================
// Kernel 3: output projection  y[b][c][p] = sum_k O[b][p][k] W[k][c]
// Coalesced store via smem transpose (Cs pad 69 -> conflict-free).
// ============================================================
__global__ void out_gemm(const float* __restrict__ w,
                         float* __restrict__ out) {
    __shared__ float As[64][17];
    __shared__ float Bs[16][64];
    __shared__ float Cs[64][69];
    int b  = blockIdx.z;
    int p0 = blockIdx.x * 64;
    int n0 = blockIdx.y * 64;
    int tid = threadIdx.x;
    int tx = tid & 15, ty = tid >> 4;

    float acc[4][4] = {};
    int arow = tid >> 2;
    int ac4  = (tid & 3) * 4;
    int p    = p0 + arow;
    int bn = tid & 63, bk = tid >> 6;

    for (int kt = 0; kt < DD; kt += 16) {
        float4 av = (p < NTOK)
            ? *(const float4*)&g_o[((size_t)b * NTOK + p) * DD + kt + ac4]
            : make_float4(0,0,0,0);
        As[arow][ac4+0] = av.x; As[arow][ac4+1] = av.y;
        As[arow][ac4+2] = av.z; As[arow][ac4+3] = av.w;
        #pragma unroll
        for (int i = 0; i < 4; i++)
            Bs[bk + i*4][bn] = w[(kt + bk + i*4) * DD + n0 + bn];
        __syncthreads();
        #pragma unroll
        for (int k = 0; k < 16; k++) {
            float4 b4 = *(const float4*)&Bs[k][tx * 4];
            float bnv[4] = {b4.x, b4.y, b4.z, b4.w};
            float am[4];
            #pragma unroll
            for (int i = 0; i < 4; i++) am[i] = As[ty*4 + i][k];
            #pragma unroll
            for (int i = 0; i < 4; i++)
                #pragma unroll
                for (int j = 0; j < 4; j++)
                    acc[i][j] = fmaf(am[i], bnv[j], acc[i][j]);
        }
        __syncthreads();
    }

    #pragma unroll
    for (int i = 0; i < 4; i++)
        #pragma unroll
        for (int j = 0; j < 4; j++)
            Cs[ty*4 + i][tx*4 + j] = acc[i][j];
    __syncthreads();

    #pragma unroll
    for (int it = 0; it < 16; it++) {
        int idx = it * 256 + tid;
        int c  = idx >> 6;
        int pl = idx & 63;
        int pp = p0 + pl;
        if (pp < NTOK)
            out[((size_t)b * DD + n0 + c) * NTOK + pp] = Cs[pl][c];
    }
}

// ============================================================
extern "C" void kernel_launch(void* const* d_in, const int* in_sizes, int n_in,
                              void* d_out, int out_size) {
    const float* x          = (const float*)d_in[0];
    const float* w_qkv      = (const float*)d_in[1];
    const float* w_out      = (const float*)d_in[2];
    const float* bias_table = (const float*)d_in[3];
    const int*   rel        = (const int*)d_in[4];
    float* out = (float*)d_out;

    bias_fill<<<(HEADS * NTOK * NTOK + 255) / 256, 256>>>(bias_table, rel);
    qkv_gemm<<<dim3(NQT, 12, BB), 256>>>(x, w_qkv);
    attn_kernel<<<dim3(NQT, BB * HEADS), 256>>>();
    out_gemm<<<dim3(NQT, 4, BB), 256>>>(w_out, out);
}

// round 2
// speedup vs baseline: 1.4121x; 1.4121x over previous
#include <cuda_runtime.h>
#include <math.h>

#define BB    64
#define DD    256
#define HEADS 8
#define DH    32
#define NTOK  625
#define NPAD  640

// ---- scratch (device globals) ----
__device__ float g_q[BB*HEADS*NTOK*DH];
__device__ float g_k[BB*HEADS*NTOK*DH];
__device__ float g_v[BB*HEADS*NTOK*DH];
__device__ float g_bias[HEADS*NPAD*NPAD];
__device__ float g_o[BB*NTOK*DD];

// ================= TF32 split-mma helpers =================
__device__ __forceinline__ unsigned f2tf(float x) {
    unsigned u; asm("cvt.rna.tf32.f32 %0, %1;" : "=r"(u) : "f"(x)); return u;
}
__device__ __forceinline__ void split(float x, unsigned &h, unsigned &l) {
    h = f2tf(x);
    l = f2tf(x - __uint_as_float(h));
}
__device__ __forceinline__ void mma8(float4 &d, const unsigned a[4],
                                     unsigned b0, unsigned b1) {
    asm volatile(
        "mma.sync.aligned.m16n8k8.row.col.f32.tf32.tf32.f32 "
        "{%0,%1,%2,%3}, {%4,%5,%6,%7}, {%8,%9}, {%0,%1,%2,%3};"
        : "+f"(d.x), "+f"(d.y), "+f"(d.z), "+f"(d.w)
        : "r"(a[0]), "r"(a[1]), "r"(a[2]), "r"(a[3]), "r"(b0), "r"(b1));
}
__device__ __forceinline__ void mma3(float4 &d, const unsigned ah[4],
                                     const unsigned al[4],
                                     unsigned bh0, unsigned bh1,
                                     unsigned bl0, unsigned bl1) {
    mma8(d, ah, bh0, bh1);
    mma8(d, ah, bl0, bl1);
    mma8(d, al, bh0, bh1);
}

// ============================================================
// Kernel 0: bias_fill (j-stride padded to 640)
// ============================================================
__global__ void bias_fill(const float* __restrict__ table,
                          const int*   __restrict__ rel) {
    int idx = blockIdx.x * blockDim.x + threadIdx.x;
    const int total = HEADS * NTOK * NTOK;
    if (idx >= total) return;
    int h = idx / (NTOK * NTOK);
    int r = idx - h * (NTOK * NTOK);
    int i = r / NTOK;
    int j = r - i * NTOK;
    g_bias[(h * NPAD + i) * NPAD + j] = table[rel[r] * HEADS + h];
}

// ============================================================
// Kernel 1: QKV projection (3xTF32 mma). Block 128(M)x64(N), K=256.
// 8 warps: wm=wid&3 (M), wn=wid>>2 (N). Warp tile 32x32.
// ============================================================
__global__ __launch_bounds__(256) void qkv_mma(const float* __restrict__ x,
                                               const float* __restrict__ w) {
    __shared__ float As[16][136];   // [k][m], stride 136 -> frag LDS conflict-free
    __shared__ float Bs[16][68];    // [k][n], stride 68

    int b  = blockIdx.z;
    int p0 = blockIdx.x * 128;
    int n0 = blockIdx.y * 64;
    int tid = threadIdx.x;
    int wid = tid >> 5, lane = tid & 31;
    int wm = wid & 3, wn = wid >> 2;
    int r = lane >> 2, c = lane & 3;
    const float* xb = x + (size_t)b * DD * NTOK;

    float4 acc[2][4];
    #pragma unroll
    for (int i = 0; i < 2; i++)
        #pragma unroll
        for (int j = 0; j < 4; j++) acc[i][j] = make_float4(0,0,0,0);

    int am = tid & 127;        // A fill: m (coalesced)
    int ak = tid >> 7;         // 0..1
    int bk = tid >> 4;         // B fill: k row
    int bn4 = (tid & 15) * 4;

    for (int k0 = 0; k0 < DD; k0 += 16) {
        #pragma unroll
        for (int i = 0; i < 8; i++) {
            int kk = ak + i * 2;
            As[kk][am] = (p0 + am < NTOK) ? xb[(size_t)(k0 + kk) * NTOK + p0 + am] : 0.f;
        }
        *(float4*)&Bs[bk][bn4] = *(const float4*)&w[(size_t)(k0 + bk) * (3*DD) + n0 + bn4];
        __syncthreads();

        #pragma unroll
        for (int ktl = 0; ktl < 2; ktl++) {
            unsigned ah[2][4], al[2][4];
            #pragma unroll
            for (int mt = 0; mt < 2; mt++) {
                int mb = wm * 32 + mt * 16;
                split(As[ktl*8 + c    ][mb + r    ], ah[mt][0], al[mt][0]);
                split(As[ktl*8 + c    ][mb + r + 8], ah[mt][1], al[mt][1]);
                split(As[ktl*8 + c + 4][mb + r    ], ah[mt][2], al[mt][2]);
                split(As[ktl*8 + c + 4][mb + r + 8], ah[mt][3], al[mt][3]);
            }
            #pragma unroll
            for (int nt = 0; nt < 4; nt++) {
                int nb = wn * 32 + nt * 8 + r;
                unsigned bh0, bl0, bh1, bl1;
                split(Bs[ktl*8 + c    ][nb], bh0, bl0);
                split(Bs[ktl*8 + c + 4][nb], bh1, bl1);
                #pragma unroll
                for (int mt = 0; mt < 2; mt++)
                    mma3(acc[mt][nt], ah[mt], al[mt], bh0, bh1, bl0, bl1);
            }
        }
        __syncthreads();
    }

    // epilogue: scatter to g_q/g_k/g_v in (bh, p, e) layout, q pre-scaled
    #pragma unroll
    for (int nt = 0; nt < 4; nt++) {
        int ng0 = n0 + wn * 32 + nt * 8 + 2 * c;
        int which = ng0 >> 8;
        int h = (ng0 >> 5) & 7;
        int e = ng0 & 31;
        float* dst = (which == 0) ? g_q : (which == 1) ? g_k : g_v;
        float s = (which == 0) ? 0.17677669529663687f : 1.f;
        size_t base = (size_t)(b * HEADS + h) * NTOK * DH + e;
        #pragma unroll
        for (int mt = 0; mt < 2; mt++) {
            int p = p0 + wm * 32 + mt * 16 + r;
            if (p < NTOK)
                *(float2*)&dst[base + (size_t)p * DH] =
                    make_float2(acc[mt][nt].x * s, acc[mt][nt].y * s);
            if (p + 8 < NTOK)
                *(float2*)&dst[base + (size_t)(p + 8) * DH] =
                    make_float2(acc[mt][nt].z * s, acc[mt][nt].w * s);
        }
    }
}

// ============================================================
// Kernel 2: flash attention with 3xTF32 mma.
// Block = 128 queries x one (b,h). 8 warps, each owns 16 q-rows.
// S warp tile 16x64 (full row -> no cross-warp softmax).
// ============================================================
#define ATTN_SMEM (2*64*36*4 + 8*64*24*4)

__global__ __launch_bounds__(256) void attn_mma() {
    extern __shared__ float sm[];
    float (*Ks)[36] = (float(*)[36])sm;               // [j][e], stride 36
    float (*Vs)[36] = (float(*)[36])(sm + 64*36);     // [j][e]
    int tid = threadIdx.x;
    int wid = tid >> 5, lane = tid & 31;
    int r = lane >> 2, c = lane & 3;
    float (*Ps)[24] = (float(*)[24])(sm + 2*64*36 + wid * (64*24)); // per-warp [j][i16]

    int q0 = blockIdx.x * 128;
    int bh = blockIdx.y;
    int h = bh & 7;
    const float* qb = g_q + (size_t)bh * NTOK * DH;
    const float* kb = g_k + (size_t)bh * NTOK * DH;
    const float* vb = g_v + (size_t)bh * NTOK * DH;

    // Q fragments resident in registers (masked rows -> 0)
    unsigned qh[4][4], ql[4][4];
    int pr = q0 + wid * 16 + r;
    #pragma unroll
    for (int kt = 0; kt < 4; kt++) {
        float q00 = (pr     < NTOK) ? qb[(size_t)pr * DH + kt*8 + c    ] : 0.f;
        float q10 = (pr + 8 < NTOK) ? qb[(size_t)(pr+8) * DH + kt*8 + c] : 0.f;
        float q01 = (pr     < NTOK) ? qb[(size_t)pr * DH + kt*8 + c + 4] : 0.f;
        float q11 = (pr + 8 < NTOK) ? qb[(size_t)(pr+8) * DH + kt*8 + c + 4] : 0.f;
        split(q00, qh[kt][0], ql[kt][0]);
        split(q10, qh[kt][1], ql[kt][1]);
        split(q01, qh[kt][2], ql[kt][2]);
        split(q11, qh[kt][3], ql[kt][3]);
    }

    float4 O[4];
    #pragma unroll
    for (int i = 0; i < 4; i++) O[i] = make_float4(0,0,0,0);
    float m0 = -INFINITY, m1 = -INFINITY, l0 = 0.f, l1 = 0.f;

    for (int jt = 0; jt < 10; jt++) {
        int j0 = jt * 64;
        // stage K, V tiles (fp32, zero-padded tail)
        {
            int row = tid >> 2, e0 = (tid & 3) * 8;
            int jp = j0 + row;
            float4 k0v, k1v, v0v, v1v;
            if (jp < NTOK) {
                k0v = *(const float4*)&kb[(size_t)jp * DH + e0];
                k1v = *(const float4*)&kb[(size_t)jp * DH + e0 + 4];
                v0v = *(const float4*)&vb[(size_t)jp * DH + e0];
                v1v = *(const float4*)&vb[(size_t)jp * DH + e0 + 4];
            } else {
                k0v = make_float4(0,0,0,0); k1v = k0v; v0v = k0v; v1v = k0v;
            }
            *(float4*)&Ks[row][e0]     = k0v;
            *(float4*)&Ks[row][e0 + 4] = k1v;
            *(float4*)&Vs[row][e0]     = v0v;
            *(float4*)&Vs[row][e0 + 4] = v1v;
        }
        __syncthreads();

        // S = Q K^T : 8 n-tiles x 4 k-tiles
        float4 acc[8];
        #pragma unroll
        for (int i = 0; i < 8; i++) acc[i] = make_float4(0,0,0,0);
        #pragma unroll
        for (int kt = 0; kt < 4; kt++) {
            #pragma unroll
            for (int nt = 0; nt < 8; nt++) {
                unsigned bh0, bl0, bh1, bl1;
                split(Ks[nt*8 + r][kt*8 + c    ], bh0, bl0);
                split(Ks[nt*8 + r][kt*8 + c + 4], bh1, bl1);
                mma3(acc[nt], qh[kt], ql[kt], bh0, bh1, bl0, bl1);
            }
        }

        // bias + tail mask
        {
            const float* bp = g_bias + ((size_t)(h * NPAD + q0 + wid*16 + r)) * NPAD + j0;
            #pragma unroll
            for (int nt = 0; nt < 8; nt++) {
                float2 b0v = *(const float2*)&bp[nt*8 + 2*c];
                float2 b1v = *(const float2*)&bp[8*NPAD + nt*8 + 2*c];
                acc[nt].x += b0v.x; acc[nt].y += b0v.y;
                acc[nt].z += b1v.x; acc[nt].w += b1v.y;
            }
            if (j0 + 64 > NTOK) {
                #pragma unroll
                for (int nt = 0; nt < 8; nt++) {
                    int jc = j0 + nt*8 + 2*c;
                    if (jc     >= NTOK) { acc[nt].x = -1e30f; acc[nt].z = -1e30f; }
                    if (jc + 1 >= NTOK) { acc[nt].y = -1e30f; acc[nt].w = -1e30f; }
                }
            }
        }

        // online softmax (rows r and r+8, reduce across the 4-lane quad)
        float t0 = -INFINITY, t1 = -INFINITY;
        #pragma unroll
        for (int nt = 0; nt < 8; nt++) {
            t0 = fmaxf(t0, fmaxf(acc[nt].x, acc[nt].y));
            t1 = fmaxf(t1, fmaxf(acc[nt].z, acc[nt].w));
        }
        #pragma unroll
        for (int off = 1; off <= 2; off <<= 1) {
            t0 = fmaxf(t0, __shfl_xor_sync(0xffffffffu, t0, off));
            t1 = fmaxf(t1, __shfl_xor_sync(0xffffffffu, t1, off));
        }
        float mn0 = fmaxf(m0, t0), mn1 = fmaxf(m1, t1);
        float cor0 = __expf(m0 - mn0), cor1 = __expf(m1 - mn1);
        float s0 = 0.f, s1 = 0.f;
        #pragma unroll
        for (int nt = 0; nt < 8; nt++) {
            acc[nt].x = __expf(acc[nt].x - mn0);
            acc[nt].y = __expf(acc[nt].y - mn0);
            acc[nt].z = __expf(acc[nt].z - mn1);
            acc[nt].w = __expf(acc[nt].w - mn1);
            s0 += acc[nt].x + acc[nt].y;
            s1 += acc[nt].z + acc[nt].w;
        }
        #pragma unroll
        for (int off = 1; off <= 2; off <<= 1) {
            s0 += __shfl_xor_sync(0xffffffffu, s0, off);
            s1 += __shfl_xor_sync(0xffffffffu, s1, off);
        }
        l0 = l0 * cor0 + s0;  m0 = mn0;
        l1 = l1 * cor1 + s1;  m1 = mn1;
        #pragma unroll
        for (int i = 0; i < 4; i++) {
            O[i].x *= cor0; O[i].y *= cor0;
            O[i].z *= cor1; O[i].w *= cor1;
        }

        // P -> per-warp transposed smem buffer [j][i]
        #pragma unroll
        for (int nt = 0; nt < 8; nt++) {
            int j = nt*8 + 2*c;
            Ps[j  ][r    ] = acc[nt].x;
            Ps[j+1][r    ] = acc[nt].y;
            Ps[j  ][r + 8] = acc[nt].z;
            Ps[j+1][r + 8] = acc[nt].w;
        }
        __syncwarp();

        // O += P V : 4 e-tiles x 8 j-k-tiles
        #pragma unroll
        for (int kt = 0; kt < 8; kt++) {
            unsigned ph[4], pl[4];
            split(Ps[kt*8 + c    ][r    ], ph[0], pl[0]);
            split(Ps[kt*8 + c    ][r + 8], ph[1], pl[1]);
            split(Ps[kt*8 + c + 4][r    ], ph[2], pl[2]);
            split(Ps[kt*8 + c + 4][r + 8], ph[3], pl[3]);
            #pragma unroll
            for (int nt = 0; nt < 4; nt++) {
                unsigned bh0, bl0, bh1, bl1;
                split(Vs[kt*8 + c    ][nt*8 + r], bh0, bl0);
                split(Vs[kt*8 + c + 4][nt*8 + r], bh1, bl1);
                mma3(O[nt], ph, pl, bh0, bh1, bl0, bl1);
            }
        }
        __syncthreads();
    }

    // epilogue: O/l -> g_o[b][p][h*32+e]
    float inv0 = 1.f / l0, inv1 = 1.f / l1;
    float* ob = g_o + (size_t)(bh >> 3) * NTOK * DD + h * DH;
    #pragma unroll
    for (int nt = 0; nt < 4; nt++) {
        int e = nt*8 + 2*c;
        int p = q0 + wid*16 + r;
        if (p < NTOK)
            *(float2*)&ob[(size_t)p * DD + e] =
                make_float2(O[nt].x * inv0, O[nt].y * inv0);
        if (p + 8 < NTOK)
            *(float2*)&ob[(size_t)(p + 8) * DD + e] =
                make_float2(O[nt].z * inv1, O[nt].w * inv1);
    }
}

// ============================================================
// Kernel 3: output projection (3xTF32 mma) + transposed store.
// Block 128(M)x64(N), K=256.
// ============================================================
__global__ __launch_bounds__(256) void out_mma(const float* __restrict__ w,
                                               float* __restrict__ out) {
    __shared__ float As[16][136];
    __shared__ float Bs[16][68];
    __shared__ float Cs[128][69];

    int b  = blockIdx.z;
    int p0 = blockIdx.x * 128;
    int n0 = blockIdx.y * 64;
    int tid = threadIdx.x;
    int wid = tid >> 5, lane = tid & 31;
    int wm = wid & 3, wn = wid >> 2;
    int r = lane >> 2, c = lane & 3;

    float4 acc[2][4];
    #pragma unroll
    for (int i = 0; i < 2; i++)
        #pragma unroll
        for (int j = 0; j < 4; j++) acc[i][j] = make_float4(0,0,0,0);

    int ap = tid >> 2;          // A fill row (first half)
    int ak4 = (tid & 3) * 4;
    int bk = tid >> 4;
    int bn4 = (tid & 15) * 4;

    for (int k0 = 0; k0 < DD; k0 += 16) {
        #pragma unroll
        for (int half = 0; half < 2; half++) {
            int pl = ap + half * 64;
            float4 v = (p0 + pl < NTOK)
                ? *(const float4*)&g_o[((size_t)b * NTOK + p0 + pl) * DD + k0 + ak4]
                : make_float4(0,0,0,0);
            As[ak4 + 0][pl] = v.x;
            As[ak4 + 1][pl] = v.y;
            As[ak4 + 2][pl] = v.z;
            As[ak4 + 3][pl] = v.w;
        }
        *(float4*)&Bs[bk][bn4] = *(const float4*)&w[(size_t)(k0 + bk) * DD + n0 + bn4];
        __syncthreads();

        #pragma unroll
        for (int ktl = 0; ktl < 2; ktl++) {
            unsigned ah[2][4], al[2][4];
            #pragma unroll
            for (int mt = 0; mt < 2; mt++) {
                int mb = wm * 32 + mt * 16;
                split(As[ktl*8 + c    ][mb + r    ], ah[mt][0], al[mt][0]);
                split(As[ktl*8 + c    ][mb + r + 8], ah[mt][1], al[mt][1]);
                split(As[ktl*8 + c + 4][mb + r    ], ah[mt][2], al[mt][2]);
                split(As[ktl*8 + c + 4][mb + r + 8], ah[mt][3], al[mt][3]);
            }
            #pragma unroll
            for (int nt = 0; nt < 4; nt++) {
                int nb = wn * 32 + nt * 8 + r;
                unsigned bh0, bl0, bh1, bl1;
                split(Bs[ktl*8 + c    ][nb], bh0, bl0);
                split(Bs[ktl*8 + c + 4][nb], bh1, bl1);
                #pragma unroll
                for (int mt = 0; mt < 2; mt++)
                    mma3(acc[mt][nt], ah[mt], al[mt], bh0, bh1, bl0, bl1);
            }
        }
        __syncthreads();
    }

    // C -> smem -> coalesced transposed store
    #pragma unroll
    for (int mt = 0; mt < 2; mt++) {
        int m = wm * 32 + mt * 16 + r;
        #pragma unroll
        for (int nt = 0; nt < 4; nt++) {
            int n = wn * 32 + nt * 8 + 2 * c;
            Cs[m    ][n    ] = acc[mt][nt].x;
            Cs[m    ][n + 1] = acc[mt][nt].y;
            Cs[m + 8][n    ] = acc[mt][nt].z;
            Cs[m + 8][n + 1] = acc[mt][nt].w;
        }
    }
    __syncthreads();

    #pragma unroll
    for (int it = 0; it < 32; it++) {
        int idx = it * 256 + tid;
        int n = idx >> 7;
        int m = idx & 127;
        int p = p0 + m;
        if (p < NTOK)
            out[((size_t)b * DD + n0 + n) * NTOK + p] = Cs[m][n];
    }
}

// ============================================================
extern "C" void kernel_launch(void* const* d_in, const int* in_sizes, int n_in,
                              void* d_out, int out_size) {
    const float* x          = (const float*)d_in[0];
    const float* w_qkv      = (const float*)d_in[1];
    const float* w_out      = (const float*)d_in[2];
    const float* bias_table = (const float*)d_in[3];
    const int*   rel        = (const int*)d_in[4];
    float* out = (float*)d_out;

    cudaFuncSetAttribute(attn_mma, cudaFuncAttributeMaxDynamicSharedMemorySize,
                         ATTN_SMEM);

    bias_fill<<<(HEADS * NTOK * NTOK + 255) / 256, 256>>>(bias_table, rel);
    qkv_mma<<<dim3(5, 12, BB), 256>>>(x, w_qkv);
    attn_mma<<<dim3(5, BB * HEADS), 256, ATTN_SMEM>>>();
    out_mma<<<dim3(5, 4, BB), 256>>>(w_out, out);
}